// round 1
// baseline (speedup 1.0000x reference)
#include <cuda_runtime.h>
#include <math.h>

#define ALPHA 0.2f

#define BB   32
#define NN   512
#define FIN  128
#define FH   64
#define NHE  8
#define NC   16

// ---------------- scratch (device globals; no allocations allowed) ----------
__device__ float    g_h1[NHE * BB * NN * FH];        // per-head hidden  (32MB)
__device__ float4   g_rc1[NHE * BB * NN];            // f1, e^f1, e^(a*f1)
__device__ float4   g_cc1[NHE * BB * NN];            // f2, e^f2, e^(a*f2)
__device__ unsigned g_mask[BB * NN * (NN / 32)];     // adj bitmask (1MB)
__device__ float    g_xcat[BB * NN * (NHE * FH)];    // concat features (32MB)
__device__ float    g_h2[BB * NN * NC];
__device__ float4   g_rc2[BB * NN];
__device__ float4   g_cc2[BB * NN];

// ---------------- f32x2 packed-FMA helpers (Blackwell) -----------------------
__device__ __forceinline__ unsigned long long pk2(float w) {
    unsigned long long r;
    asm("mov.b64 %0, {%1, %1};" : "=l"(r) : "f"(w));
    return r;
}
__device__ __forceinline__ void ffma2(unsigned long long& d,
                                      unsigned long long a,
                                      unsigned long long b) {
    asm("fma.rn.f32x2 %0, %1, %2, %3;" : "=l"(d) : "l"(a), "l"(b), "l"(d));
}
__device__ __forceinline__ float2 upk2(unsigned long long v) {
    float2 r;
    asm("mov.b64 {%0, %1}, %2;" : "=f"(r.x), "=f"(r.y) : "l"(v));
    return r;
}

// ---------------- adj -> bitmask --------------------------------------------
__global__ __launch_bounds__(256) void maskpack_kernel(const int* __restrict__ adj) {
    const int warp = blockIdx.x * 8 + (threadIdx.x >> 5);
    const int lane = threadIdx.x & 31;
    const int b = warp / NN;
    const int i = warp % NN;
    const int* row = adj + ((size_t)b * NN + i) * NN;
    unsigned* dst = g_mask + ((size_t)b * NN + i) * (NN / 32);
#pragma unroll
    for (int w = 0; w < NN / 32; w++) {
        int v = row[w * 32 + lane];
        unsigned m = __ballot_sync(0xffffffffu, v > 0);
        if (lane == 0) dst[w] = m;
    }
}

// ---------------- layer-1 projection: h = x@W, f1/f2, exps -------------------
// grid (N/32, B, H), 256 threads. 32 rows x 64 cols per block, K=128.
__global__ __launch_bounds__(256) void proj1_kernel(
    const float* __restrict__ x, const float* __restrict__ Wh,
    const float* __restrict__ a1h, const float* __restrict__ a2h) {
    __shared__ float xs[32 * FIN];   // 16KB (reused as padded h stage)
    __shared__ float Ws[FIN * FH];   // 32KB
    const int rt = blockIdx.x, b = blockIdx.y, h = blockIdx.z;
    const int tid = threadIdx.x;

    const float* xg = x + ((size_t)b * NN + rt * 32) * FIN;
#pragma unroll
    for (int u = 0; u < 4; u++)
        ((float4*)xs)[tid + u * 256] = ((const float4*)xg)[tid + u * 256];
    const float* Wg = Wh + (size_t)h * FIN * FH;
#pragma unroll
    for (int u = 0; u < 8; u++)
        ((float4*)Ws)[tid + u * 256] = ((const float4*)Wg)[tid + u * 256];
    __syncthreads();

    const int col = tid & 63;
    const int r0 = (tid >> 6) * 8;
    float acc[8] = {0.f, 0.f, 0.f, 0.f, 0.f, 0.f, 0.f, 0.f};

#pragma unroll 2
    for (int k = 0; k < FIN; k += 4) {
        float w0 = Ws[(k + 0) * FH + col];
        float w1 = Ws[(k + 1) * FH + col];
        float w2 = Ws[(k + 2) * FH + col];
        float w3 = Ws[(k + 3) * FH + col];
#pragma unroll
        for (int r = 0; r < 8; r++) {
            float4 xv = *(const float4*)&xs[(r0 + r) * FIN + k];
            acc[r] = fmaf(xv.x, w0, acc[r]);
            acc[r] = fmaf(xv.y, w1, acc[r]);
            acc[r] = fmaf(xv.z, w2, acc[r]);
            acc[r] = fmaf(xv.w, w3, acc[r]);
        }
    }

    float* outg = g_h1 + (((size_t)(h * BB + b) * NN) + rt * 32) * FH;
    __syncthreads();              // done reading xs -> safe to reuse
    float* hs = xs;               // stride 65 (bank-conflict-free reduce)
#pragma unroll
    for (int r = 0; r < 8; r++) {
        outg[(r0 + r) * FH + col] = acc[r];
        hs[(r0 + r) * 65 + col] = acc[r];
    }
    __syncthreads();

    if (tid < 32) {
        const float* a1 = a1h + h * FH;
        const float* a2 = a2h + h * FH;
        float f1 = 0.f, f2 = 0.f;
#pragma unroll 4
        for (int c = 0; c < FH; c++) {
            float v = hs[tid * 65 + c];
            f1 = fmaf(v, a1[c], f1);
            f2 = fmaf(v, a2[c], f2);
        }
        int idx = (h * BB + b) * NN + rt * 32 + tid;
        g_rc1[idx] = make_float4(f1, expf(f1), expf(ALPHA * f1), 0.f);
        g_cc1[idx] = make_float4(f2, expf(f2), expf(ALPHA * f2), 0.f);
    }
}

// ---------------- layer-1 attention + ELU + concat write ---------------------
// grid (N/64, B, H), 256 threads. i-tile 64 x 64 cols, j tiles of 32.
__global__ __launch_bounds__(256) void attn1_kernel() {
    __shared__ float hj[32 * FH];                 // 8KB  j-tile of h
    __shared__ unsigned long long ws2[32 * 64];   // 16KB packed weights [jj][i]
    __shared__ float zs[4 * 64];
    __shared__ float zinv[64];

    const int it = blockIdx.x, b = blockIdx.y, h = blockIdx.z;
    const int i0 = it * 64;
    const int tid = threadIdx.x;

    // weight-gen role: row = tid&63, jj group = tid>>6 (8 jj each)
    const int wrow = tid & 63, wg = tid >> 6;
    const float4 rc = g_rc1[(h * BB + b) * NN + i0 + wrow];
    const unsigned* mrow = g_mask + ((size_t)b * NN + i0 + wrow) * (NN / 32);
    const float4* ccg = g_cc1 + (h * BB + b) * NN;
    const float* hbase = g_h1 + ((size_t)(h * BB + b) * NN) * FH;
    float zacc = 0.f;

    // GEMM role: 4 rows x 4 cols per thread
    const int tx = tid & 15, ty = tid >> 4;
    const int c0 = tx * 4, r0 = ty * 4;
    unsigned long long acc[4][2];
#pragma unroll
    for (int r = 0; r < 4; r++) { acc[r][0] = 0ull; acc[r][1] = 0ull; }

    for (int jt = 0; jt < NN / 32; jt++) {
        __syncthreads();  // previous GEMM finished before overwrite
        // load h j-tile: 2048 floats
        const float4* src = (const float4*)(hbase + (size_t)jt * 32 * FH);
        ((float4*)hj)[tid] = src[tid];
        ((float4*)hj)[tid + 256] = src[tid + 256];
        // weight generation (exp-free): w = mask * sel(s>=0, E1*F1, E2*F2)
        unsigned mw = mrow[jt];
#pragma unroll
        for (int u = 0; u < 8; u++) {
            int jj = wg * 8 + u;
            float4 c = ccg[jt * 32 + jj];
            float s = rc.x + c.x;
            float p = (s >= 0.f) ? rc.y * c.y : rc.z * c.z;
            float w = ((mw >> jj) & 1u) ? p : 0.f;
            zacc += w;
            ws2[jj * 64 + wrow] = pk2(w);
        }
        __syncthreads();
#pragma unroll 4
        for (int jj = 0; jj < 32; jj++) {
            ulonglong2 wa = *(const ulonglong2*)&ws2[jj * 64 + r0];       // rows r0,r0+1
            ulonglong2 wb = *(const ulonglong2*)&ws2[jj * 64 + r0 + 2];   // rows r0+2,r0+3
            ulonglong2 hv = *(const ulonglong2*)&hj[jj * FH + c0];        // cols c0..c0+3
            ffma2(acc[0][0], wa.x, hv.x); ffma2(acc[0][1], wa.x, hv.y);
            ffma2(acc[1][0], wa.y, hv.x); ffma2(acc[1][1], wa.y, hv.y);
            ffma2(acc[2][0], wb.x, hv.x); ffma2(acc[2][1], wb.x, hv.y);
            ffma2(acc[3][0], wb.y, hv.x); ffma2(acc[3][1], wb.y, hv.y);
        }
    }

    zs[wg * 64 + wrow] = zacc;
    __syncthreads();
    if (tid < 64)
        zinv[tid] = 1.f / (zs[tid] + zs[64 + tid] + zs[128 + tid] + zs[192 + tid]);
    __syncthreads();

    float* outb = g_xcat + ((size_t)b * NN + i0) * (NHE * FH) + h * FH;
#pragma unroll
    for (int r = 0; r < 4; r++) {
        float zi = zinv[r0 + r];
        float2 v0 = upk2(acc[r][0]);
        float2 v1 = upk2(acc[r][1]);
        float4 o;
        o.x = v0.x * zi; o.y = v0.y * zi; o.z = v1.x * zi; o.w = v1.y * zi;
        o.x = o.x > 0.f ? o.x : expm1f(o.x);
        o.y = o.y > 0.f ? o.y : expm1f(o.y);
        o.z = o.z > 0.f ? o.z : expm1f(o.z);
        o.w = o.w > 0.f ? o.w : expm1f(o.w);
        *(float4*)(outb + (size_t)(r0 + r) * (NHE * FH) + c0) = o;
    }
}

// ---------------- layer-2 projection: h2 = x_cat@W_out, g1/g2, exps ----------
// grid (N/32, B), 256 threads. 32 rows x 16 cols, K=512 in chunks of 128.
__global__ __launch_bounds__(256) void proj2_kernel(
    const float* __restrict__ Wo, const float* __restrict__ a1o,
    const float* __restrict__ a2o) {
    __shared__ float xs[32 * 128];   // 16KB
    __shared__ float Wc[128 * NC];   // 8KB
    __shared__ float h2s[32 * 17];   // padded stage
    const int rt = blockIdx.x, b = blockIdx.y;
    const int tid = threadIdx.x;
    const int col = tid & 15;
    const int r0 = (tid >> 4) * 2;
    float acc0 = 0.f, acc1 = 0.f;
    const float* xg = g_xcat + ((size_t)b * NN + rt * 32) * (NHE * FH);

    for (int kc = 0; kc < 4; kc++) {
        __syncthreads();
#pragma unroll
        for (int u = 0; u < 4; u++) {
            int idx = tid + u * 256;     // float4 index, 32 per row
            int row = idx >> 5, kk = idx & 31;
            ((float4*)&xs[row * 128])[kk] =
                ((const float4*)(xg + (size_t)row * (NHE * FH) + kc * 128))[kk];
        }
#pragma unroll
        for (int u = 0; u < 2; u++)
            ((float4*)Wc)[tid + u * 256] =
                ((const float4*)(Wo + (size_t)kc * 128 * NC))[tid + u * 256];
        __syncthreads();
#pragma unroll 4
        for (int k = 0; k < 128; k += 4) {
            float4 xa = *(const float4*)&xs[r0 * 128 + k];
            float4 xb = *(const float4*)&xs[(r0 + 1) * 128 + k];
            float w0 = Wc[(k + 0) * NC + col];
            float w1 = Wc[(k + 1) * NC + col];
            float w2 = Wc[(k + 2) * NC + col];
            float w3 = Wc[(k + 3) * NC + col];
            acc0 = fmaf(xa.x, w0, acc0); acc0 = fmaf(xa.y, w1, acc0);
            acc0 = fmaf(xa.z, w2, acc0); acc0 = fmaf(xa.w, w3, acc0);
            acc1 = fmaf(xb.x, w0, acc1); acc1 = fmaf(xb.y, w1, acc1);
            acc1 = fmaf(xb.z, w2, acc1); acc1 = fmaf(xb.w, w3, acc1);
        }
    }

    __syncthreads();
    h2s[(r0 + 0) * 17 + col] = acc0;
    h2s[(r0 + 1) * 17 + col] = acc1;
    g_h2[((size_t)b * NN + rt * 32 + r0 + 0) * NC + col] = acc0;
    g_h2[((size_t)b * NN + rt * 32 + r0 + 1) * NC + col] = acc1;
    __syncthreads();

    if (tid < 32) {
        float g1 = 0.f, g2 = 0.f;
#pragma unroll
        for (int c = 0; c < NC; c++) {
            float v = h2s[tid * 17 + c];
            g1 = fmaf(v, a1o[c], g1);
            g2 = fmaf(v, a2o[c], g2);
        }
        int idx = b * NN + rt * 32 + tid;
        g_rc2[idx] = make_float4(g1, expf(g1), expf(ALPHA * g1), 0.f);
        g_cc2[idx] = make_float4(g2, expf(g2), expf(ALPHA * g2), 0.f);
    }
}

// ---------------- layer-2 attention (no ELU) -> output -----------------------
// grid (N/32, B), 256 threads. i-tile 32 x 16 cols, j tiles of 64.
__global__ __launch_bounds__(256) void attn2_kernel(float* __restrict__ out) {
    __shared__ float h2s[64 * NC];                 // 4KB
    __shared__ unsigned long long ws2[64 * 32];    // 16KB [jj][i]
    __shared__ float zs[8 * 32];
    __shared__ float zinv[32];

    const int it = blockIdx.x, b = blockIdx.y;
    const int i0 = it * 32;
    const int tid = threadIdx.x;

    const int wrow = tid & 31, wg = tid >> 5;   // wg 0..7, 8 jj each
    const float4 rc = g_rc2[b * NN + i0 + wrow];
    const unsigned* mrow = g_mask + ((size_t)b * NN + i0 + wrow) * (NN / 32);
    const float4* ccg = g_cc2 + b * NN;
    const float* hbase = g_h2 + (size_t)b * NN * NC;
    float zacc = 0.f;

    const int gcol = (tid & 7) * 2, grow = tid >> 3;   // 32 rows x 8 col-pairs
    unsigned long long acc = 0ull;

    for (int jt = 0; jt < NN / 64; jt++) {
        __syncthreads();
        ((float4*)h2s)[tid] = ((const float4*)(hbase + (size_t)jt * 64 * NC))[tid];
        unsigned mw = mrow[jt * 2 + (wg >> 2)];
#pragma unroll
        for (int u = 0; u < 8; u++) {
            int jj = wg * 8 + u;
            float4 c = ccg[jt * 64 + jj];
            float s = rc.x + c.x;
            float p = (s >= 0.f) ? rc.y * c.y : rc.z * c.z;
            float w = ((mw >> (jj & 31)) & 1u) ? p : 0.f;
            zacc += w;
            ws2[jj * 32 + wrow] = pk2(w);
        }
        __syncthreads();
#pragma unroll 8
        for (int jj = 0; jj < 64; jj++) {
            unsigned long long hv = *(const unsigned long long*)&h2s[jj * NC + gcol];
            ffma2(acc, ws2[jj * 32 + grow], hv);
        }
    }

    zs[wg * 32 + wrow] = zacc;
    __syncthreads();
    if (tid < 32) {
        float z = 0.f;
#pragma unroll
        for (int g = 0; g < 8; g++) z += zs[g * 32 + tid];
        zinv[tid] = 1.f / z;
    }
    __syncthreads();

    float zi = zinv[grow];
    float2 v = upk2(acc);
    float2 o = make_float2(v.x * zi, v.y * zi);
    *(float2*)(out + ((size_t)b * NN + i0 + grow) * NC + gcol) = o;
}

// ---------------- launcher ---------------------------------------------------
extern "C" void kernel_launch(void* const* d_in, const int* in_sizes, int n_in,
                              void* d_out, int out_size) {
    const float* x   = (const float*)d_in[0];
    const int*   adj = (const int*)d_in[1];
    const float* Wh  = (const float*)d_in[2];
    const float* a1h = (const float*)d_in[3];
    const float* a2h = (const float*)d_in[4];
    const float* Wo  = (const float*)d_in[5];
    const float* a1o = (const float*)d_in[6];
    const float* a2o = (const float*)d_in[7];
    float* out = (float*)d_out;

    maskpack_kernel<<<BB * NN / 8, 256>>>(adj);
    proj1_kernel<<<dim3(NN / 32, BB, NHE), 256>>>(x, Wh, a1h, a2h);
    attn1_kernel<<<dim3(NN / 64, BB, NHE), 256>>>();
    proj2_kernel<<<dim3(NN / 32, BB), 256>>>(Wo, a1o, a2o);
    attn2_kernel<<<dim3(NN / 32, BB), 256>>>(out);
}

// round 16
// speedup vs baseline: 1.1345x; 1.1345x over previous
#include <cuda_runtime.h>
#include <math.h>
#include <stdint.h>

#define ALPHA 0.2f

#define BB   32
#define NN   512
#define FIN  128
#define FH   64
#define NHE  8
#define NC   16

// ---------------- scratch (device globals; no allocations allowed) ----------
__device__ float    g_h1[NHE * BB * NN * FH];        // per-head hidden  (32MB)
__device__ float4   g_rc1[NHE * BB * NN];            // f1, e^f1, e^(a*f1)
__device__ float4   g_cc1[NHE * BB * NN];            // f2, e^f2, e^(a*f2)
__device__ unsigned g_mask[BB * NN * (NN / 32)];     // adj bitmask (1MB)
__device__ float    g_xcat[BB * NN * (NHE * FH)];    // concat features (32MB)
__device__ float    g_h2[BB * NN * NC];
__device__ float4   g_rc2[BB * NN];
__device__ float4   g_cc2[BB * NN];

// ---------------- f32x2 packed-FMA helpers (Blackwell) -----------------------
__device__ __forceinline__ unsigned long long pk2(float w) {
    unsigned long long r;
    asm("mov.b64 %0, {%1, %1};" : "=l"(r) : "f"(w));
    return r;
}
__device__ __forceinline__ void ffma2(unsigned long long& d,
                                      unsigned long long a,
                                      unsigned long long b) {
    asm("fma.rn.f32x2 %0, %1, %2, %3;" : "=l"(d) : "l"(a), "l"(b), "l"(d));
}
__device__ __forceinline__ float2 upk2(unsigned long long v) {
    float2 r;
    asm("mov.b64 {%0, %1}, %2;" : "=f"(r.x), "=f"(r.y) : "l"(v));
    return r;
}

// ---------------- adj -> bitmask --------------------------------------------
__global__ __launch_bounds__(256) void maskpack_kernel(const int* __restrict__ adj) {
    const int warp = blockIdx.x * 8 + (threadIdx.x >> 5);
    const int lane = threadIdx.x & 31;
    const int b = warp / NN;
    const int i = warp % NN;
    const int* row = adj + ((size_t)b * NN + i) * NN;
    unsigned* dst = g_mask + ((size_t)b * NN + i) * (NN / 32);
#pragma unroll
    for (int w = 0; w < NN / 32; w++) {
        int v = row[w * 32 + lane];
        unsigned m = __ballot_sync(0xffffffffu, v > 0);
        if (lane == 0) dst[w] = m;
    }
}

// ---------------- layer-1 projection: h = x@W, f1/f2, exps -------------------
__global__ __launch_bounds__(256) void proj1_kernel(
    const float* __restrict__ x, const float* __restrict__ Wh,
    const float* __restrict__ a1h, const float* __restrict__ a2h) {
    __shared__ float xs[32 * FIN];
    __shared__ float Ws[FIN * FH];
    const int rt = blockIdx.x, b = blockIdx.y, h = blockIdx.z;
    const int tid = threadIdx.x;

    const float* xg = x + ((size_t)b * NN + rt * 32) * FIN;
#pragma unroll
    for (int u = 0; u < 4; u++)
        ((float4*)xs)[tid + u * 256] = ((const float4*)xg)[tid + u * 256];
    const float* Wg = Wh + (size_t)h * FIN * FH;
#pragma unroll
    for (int u = 0; u < 8; u++)
        ((float4*)Ws)[tid + u * 256] = ((const float4*)Wg)[tid + u * 256];
    __syncthreads();

    const int col = tid & 63;
    const int r0 = (tid >> 6) * 8;
    float acc[8] = {0.f, 0.f, 0.f, 0.f, 0.f, 0.f, 0.f, 0.f};

#pragma unroll 2
    for (int k = 0; k < FIN; k += 4) {
        float w0 = Ws[(k + 0) * FH + col];
        float w1 = Ws[(k + 1) * FH + col];
        float w2 = Ws[(k + 2) * FH + col];
        float w3 = Ws[(k + 3) * FH + col];
#pragma unroll
        for (int r = 0; r < 8; r++) {
            float4 xv = *(const float4*)&xs[(r0 + r) * FIN + k];
            acc[r] = fmaf(xv.x, w0, acc[r]);
            acc[r] = fmaf(xv.y, w1, acc[r]);
            acc[r] = fmaf(xv.z, w2, acc[r]);
            acc[r] = fmaf(xv.w, w3, acc[r]);
        }
    }

    float* outg = g_h1 + (((size_t)(h * BB + b) * NN) + rt * 32) * FH;
    __syncthreads();
    float* hs = xs;
#pragma unroll
    for (int r = 0; r < 8; r++) {
        outg[(r0 + r) * FH + col] = acc[r];
        hs[(r0 + r) * 65 + col] = acc[r];
    }
    __syncthreads();

    if (tid < 32) {
        const float* a1 = a1h + h * FH;
        const float* a2 = a2h + h * FH;
        float f1 = 0.f, f2 = 0.f;
#pragma unroll 4
        for (int c = 0; c < FH; c++) {
            float v = hs[tid * 65 + c];
            f1 = fmaf(v, a1[c], f1);
            f2 = fmaf(v, a2[c], f2);
        }
        int idx = (h * BB + b) * NN + rt * 32 + tid;
        g_rc1[idx] = make_float4(f1, expf(f1), expf(ALPHA * f1), 0.f);
        g_cc1[idx] = make_float4(f2, expf(f2), expf(ALPHA * f2), 0.f);
    }
}

// ---------------- layer-1 attention via mma.sync tf32 (sm_80 path) ----------
// grid (N/128, B, H), 256 threads. Warp w: rows w*16..+15 (m16 frag rows
// gid,+8), all 64 cols (8 n-tiles of 8). j looped in 64-chunks, k-steps of 8.
__global__ __launch_bounds__(256) void attn1_mma_kernel() {
    __shared__ float hs[64 * 64];        // h tile, XOR-swizzled (16KB)
    __shared__ float4 ccs[64];           // cc stage (1KB)
    __shared__ unsigned msk[128 * 16];   // mask rows (8KB)
    __shared__ float zs[128];

    const int tid = threadIdx.x;
    const int warp = tid >> 5, lane = tid & 31;
    const int gid = lane >> 2, ctg = lane & 3;
    const int it = blockIdx.x, b = blockIdx.y, h = blockIdx.z;
    const int i0 = it * 128;

    // stage mask rows (contiguous 2048 words for rows i0..i0+127)
    const unsigned* mg = g_mask + ((size_t)b * NN + i0) * (NN / 32);
#pragma unroll
    for (int q = 0; q < 8; q++) msk[q * 256 + tid] = mg[q * 256 + tid];

    const int r0l = warp * 16 + gid;                 // local rows r0l, r0l+8
    const float4 rc0 = g_rc1[(h * BB + b) * NN + i0 + r0l];
    const float4 rc1 = g_rc1[(h * BB + b) * NN + i0 + r0l + 8];
    const float4* ccg = g_cc1 + (h * BB + b) * NN;
    const float* hbase = g_h1 + ((size_t)(h * BB + b) * NN) * FH;

    float d[8][4];
#pragma unroll
    for (int nt = 0; nt < 8; nt++) {
        d[nt][0] = 0.f; d[nt][1] = 0.f; d[nt][2] = 0.f; d[nt][3] = 0.f;
    }
    float zacc0 = 0.f, zacc1 = 0.f;

    for (int jc = 0; jc < 8; jc++) {
        __syncthreads();
        // load h tile [64 j][64 f] with swizzle f ^= (j&3)<<3
        const float4* hsrc = (const float4*)(hbase + (size_t)jc * 64 * FH);
#pragma unroll
        for (int q = 0; q < 4; q++) {
            int idx = q * 256 + tid;
            int j = idx >> 4, f4 = (idx & 15) << 2;
            float4 v = hsrc[idx];
            *(float4*)&hs[j * 64 + (f4 ^ ((j & 3) << 3))] = v;
        }
        if (tid < 64) ccs[tid] = ccg[jc * 64 + tid];
        __syncthreads();

        const unsigned mw0a = msk[r0l * 16 + jc * 2];
        const unsigned mw0b = msk[r0l * 16 + jc * 2 + 1];
        const unsigned mw1a = msk[(r0l + 8) * 16 + jc * 2];
        const unsigned mw1b = msk[(r0l + 8) * 16 + jc * 2 + 1];

#pragma unroll
        for (int ks = 0; ks < 8; ks++) {
            const int jl = ks * 8;
            const float4 c0 = ccs[jl + ctg];
            const float4 c1 = ccs[jl + ctg + 4];
            const unsigned m0 = (ks < 4) ? mw0a : mw0b;
            const unsigned m1 = (ks < 4) ? mw1a : mw1b;
            const int bit0 = (jl + ctg) & 31, bit1 = (jl + ctg + 4) & 31;

            uint32_t a0, a1, a2, a3;
            {
                float s = rc0.x + c0.x;
                float p = (s >= 0.f) ? rc0.y * c0.y : rc0.z * c0.z;
                float w = ((m0 >> bit0) & 1u) ? p : 0.f;
                asm("cvt.rna.tf32.f32 %0, %1;" : "=r"(a0) : "f"(w));
                zacc0 += __uint_as_float(a0);
            }
            {
                float s = rc1.x + c0.x;
                float p = (s >= 0.f) ? rc1.y * c0.y : rc1.z * c0.z;
                float w = ((m1 >> bit0) & 1u) ? p : 0.f;
                asm("cvt.rna.tf32.f32 %0, %1;" : "=r"(a1) : "f"(w));
                zacc1 += __uint_as_float(a1);
            }
            {
                float s = rc0.x + c1.x;
                float p = (s >= 0.f) ? rc0.y * c1.y : rc0.z * c1.z;
                float w = ((m0 >> bit1) & 1u) ? p : 0.f;
                asm("cvt.rna.tf32.f32 %0, %1;" : "=r"(a2) : "f"(w));
                zacc0 += __uint_as_float(a2);
            }
            {
                float s = rc1.x + c1.x;
                float p = (s >= 0.f) ? rc1.y * c1.y : rc1.z * c1.z;
                float w = ((m1 >> bit1) & 1u) ? p : 0.f;
                asm("cvt.rna.tf32.f32 %0, %1;" : "=r"(a3) : "f"(w));
                zacc1 += __uint_as_float(a3);
            }

            const int jb0 = (jl + ctg) * 64;
            const int jb1 = (jl + ctg + 4) * 64;
            const int sw = ctg << 3;   // (j&3)<<3, same for both rows
#pragma unroll
            for (int nt = 0; nt < 8; nt++) {
                const int f = nt * 8 + gid;
                uint32_t b0 = __float_as_uint(hs[jb0 + (f ^ sw)]);
                uint32_t b1 = __float_as_uint(hs[jb1 + (f ^ sw)]);
                asm volatile(
                    "mma.sync.aligned.m16n8k8.row.col.f32.tf32.tf32.f32 "
                    "{%0,%1,%2,%3}, {%4,%5,%6,%7}, {%8,%9}, {%0,%1,%2,%3};"
                    : "+f"(d[nt][0]), "+f"(d[nt][1]), "+f"(d[nt][2]), "+f"(d[nt][3])
                    : "r"(a0), "r"(a1), "r"(a2), "r"(a3), "r"(b0), "r"(b1));
            }
        }
    }

    // softmax denominator: reduce over the 4 lanes of each quad (k coverage)
    zacc0 += __shfl_xor_sync(0xffffffffu, zacc0, 1);
    zacc0 += __shfl_xor_sync(0xffffffffu, zacc0, 2);
    zacc1 += __shfl_xor_sync(0xffffffffu, zacc1, 1);
    zacc1 += __shfl_xor_sync(0xffffffffu, zacc1, 2);
    if (ctg == 0) { zs[r0l] = zacc0; zs[r0l + 8] = zacc1; }
    __syncthreads();
    const float zi0 = 1.f / zs[r0l];
    const float zi1 = 1.f / zs[r0l + 8];

    // epilogue: scale, ELU, write concat slice
    float* outb = g_xcat + ((size_t)b * NN + i0) * (NHE * FH) + h * FH;
#pragma unroll
    for (int nt = 0; nt < 8; nt++) {
        const int col = nt * 8 + ctg * 2;
        float2 o0 = make_float2(d[nt][0] * zi0, d[nt][1] * zi0);
        float2 o1 = make_float2(d[nt][2] * zi1, d[nt][3] * zi1);
        o0.x = o0.x > 0.f ? o0.x : expm1f(o0.x);
        o0.y = o0.y > 0.f ? o0.y : expm1f(o0.y);
        o1.x = o1.x > 0.f ? o1.x : expm1f(o1.x);
        o1.y = o1.y > 0.f ? o1.y : expm1f(o1.y);
        *(float2*)(outb + (size_t)r0l * (NHE * FH) + col) = o0;
        *(float2*)(outb + (size_t)(r0l + 8) * (NHE * FH) + col) = o1;
    }
}

// ---------------- layer-2 projection: h2 = x_cat@W_out, g1/g2, exps ----------
__global__ __launch_bounds__(256) void proj2_kernel(
    const float* __restrict__ Wo, const float* __restrict__ a1o,
    const float* __restrict__ a2o) {
    __shared__ float xs[32 * 128];
    __shared__ float Wc[128 * NC];
    __shared__ float h2s[32 * 17];
    const int rt = blockIdx.x, b = blockIdx.y;
    const int tid = threadIdx.x;
    const int col = tid & 15;
    const int r0 = (tid >> 4) * 2;
    float acc0 = 0.f, acc1 = 0.f;
    const float* xg = g_xcat + ((size_t)b * NN + rt * 32) * (NHE * FH);

    for (int kc = 0; kc < 4; kc++) {
        __syncthreads();
#pragma unroll
        for (int u = 0; u < 4; u++) {
            int idx = tid + u * 256;
            int row = idx >> 5, kk = idx & 31;
            ((float4*)&xs[row * 128])[kk] =
                ((const float4*)(xg + (size_t)row * (NHE * FH) + kc * 128))[kk];
        }
#pragma unroll
        for (int u = 0; u < 2; u++)
            ((float4*)Wc)[tid + u * 256] =
                ((const float4*)(Wo + (size_t)kc * 128 * NC))[tid + u * 256];
        __syncthreads();
#pragma unroll 4
        for (int k = 0; k < 128; k += 4) {
            float4 xa = *(const float4*)&xs[r0 * 128 + k];
            float4 xb = *(const float4*)&xs[(r0 + 1) * 128 + k];
            float w0 = Wc[(k + 0) * NC + col];
            float w1 = Wc[(k + 1) * NC + col];
            float w2 = Wc[(k + 2) * NC + col];
            float w3 = Wc[(k + 3) * NC + col];
            acc0 = fmaf(xa.x, w0, acc0); acc0 = fmaf(xa.y, w1, acc0);
            acc0 = fmaf(xa.z, w2, acc0); acc0 = fmaf(xa.w, w3, acc0);
            acc1 = fmaf(xb.x, w0, acc1); acc1 = fmaf(xb.y, w1, acc1);
            acc1 = fmaf(xb.z, w2, acc1); acc1 = fmaf(xb.w, w3, acc1);
        }
    }

    __syncthreads();
    h2s[(r0 + 0) * 17 + col] = acc0;
    h2s[(r0 + 1) * 17 + col] = acc1;
    g_h2[((size_t)b * NN + rt * 32 + r0 + 0) * NC + col] = acc0;
    g_h2[((size_t)b * NN + rt * 32 + r0 + 1) * NC + col] = acc1;
    __syncthreads();

    if (tid < 32) {
        float g1 = 0.f, g2 = 0.f;
#pragma unroll
        for (int c = 0; c < NC; c++) {
            float v = h2s[tid * 17 + c];
            g1 = fmaf(v, a1o[c], g1);
            g2 = fmaf(v, a2o[c], g2);
        }
        int idx = b * NN + rt * 32 + tid;
        g_rc2[idx] = make_float4(g1, expf(g1), expf(ALPHA * g1), 0.f);
        g_cc2[idx] = make_float4(g2, expf(g2), expf(ALPHA * g2), 0.f);
    }
}

// ---------------- layer-2 attention (no ELU) -> output -----------------------
__global__ __launch_bounds__(256) void attn2_kernel(float* __restrict__ out) {
    __shared__ float h2s[64 * NC];
    __shared__ unsigned long long ws2[64 * 32];
    __shared__ float zs[8 * 32];
    __shared__ float zinv[32];

    const int it = blockIdx.x, b = blockIdx.y;
    const int i0 = it * 32;
    const int tid = threadIdx.x;

    const int wrow = tid & 31, wg = tid >> 5;
    const float4 rc = g_rc2[b * NN + i0 + wrow];
    const unsigned* mrow = g_mask + ((size_t)b * NN + i0 + wrow) * (NN / 32);
    const float4* ccg = g_cc2 + b * NN;
    const float* hbase = g_h2 + (size_t)b * NN * NC;
    float zacc = 0.f;

    const int gcol = (tid & 7) * 2, grow = tid >> 3;
    unsigned long long acc = 0ull;

    for (int jt = 0; jt < NN / 64; jt++) {
        __syncthreads();
        ((float4*)h2s)[tid] = ((const float4*)(hbase + (size_t)jt * 64 * NC))[tid];
        unsigned mw = mrow[jt * 2 + (wg >> 2)];
#pragma unroll
        for (int u = 0; u < 8; u++) {
            int jj = wg * 8 + u;
            float4 c = ccg[jt * 64 + jj];
            float s = rc.x + c.x;
            float p = (s >= 0.f) ? rc.y * c.y : rc.z * c.z;
            float w = ((mw >> (jj & 31)) & 1u) ? p : 0.f;
            zacc += w;
            ws2[jj * 32 + wrow] = pk2(w);
        }
        __syncthreads();
#pragma unroll 8
        for (int jj = 0; jj < 64; jj++) {
            unsigned long long hv = *(const unsigned long long*)&h2s[jj * NC + gcol];
            ffma2(acc, ws2[jj * 32 + grow], hv);
        }
    }

    zs[wg * 32 + wrow] = zacc;
    __syncthreads();
    if (tid < 32) {
        float z = 0.f;
#pragma unroll
        for (int g = 0; g < 8; g++) z += zs[g * 32 + tid];
        zinv[tid] = 1.f / z;
    }
    __syncthreads();

    float zi = zinv[grow];
    float2 v = upk2(acc);
    float2 o = make_float2(v.x * zi, v.y * zi);
    *(float2*)(out + ((size_t)b * NN + i0 + grow) * NC + gcol) = o;
}

// ---------------- launcher ---------------------------------------------------
extern "C" void kernel_launch(void* const* d_in, const int* in_sizes, int n_in,
                              void* d_out, int out_size) {
    const float* x   = (const float*)d_in[0];
    const int*   adj = (const int*)d_in[1];
    const float* Wh  = (const float*)d_in[2];
    const float* a1h = (const float*)d_in[3];
    const float* a2h = (const float*)d_in[4];
    const float* Wo  = (const float*)d_in[5];
    const float* a1o = (const float*)d_in[6];
    const float* a2o = (const float*)d_in[7];
    float* out = (float*)d_out;

    maskpack_kernel<<<BB * NN / 8, 256>>>(adj);
    proj1_kernel<<<dim3(NN / 32, BB, NHE), 256>>>(x, Wh, a1h, a2h);
    attn1_mma_kernel<<<dim3(NN / 128, BB, NHE), 256>>>();
    proj2_kernel<<<dim3(NN / 32, BB), 256>>>(Wo, a1o, a2o);
    attn2_kernel<<<dim3(NN / 32, BB), 256>>>(out);
}